// round 6
// baseline (speedup 1.0000x reference)
#include <cuda_runtime.h>
#include <cuda_bf16.h>
#include <cstdint>

// u_quant_weight_linear: per-out-channel uniform symmetric fake quantization.
// out[o,i] = clip(rint(w[o,i]/s), -qmax, qmax) * s
//   s = max(alh[o], 1e-5); b = rint(clip(|bit[o]|,1,6)); qmax = max(2^(b-1)-1,1)
//
// R6: tail-free batch-8 tiling (5504 blocks x 256 thr x 8 = 11272192 exactly)
// + two-row trick: a 2048-vec chunk spans at most 2 rows (2048 < 2752), so
// compute both rows' (s,qmax) ONCE per thread and per-item select by
// idx >= boundary. Deletes 8 udivs + 8 exp2 chains per thread.
// __launch_bounds__(256,6) targets <=42 regs -> 75% occ, MLP_p1 = 8.

#define VEC_PER_ROW 2752u
#define LAST_ROW    4095u
#define NTHR        256
#define BATCH       8
#define CHUNK       (NTHR * BATCH)           // 2048
#define NBLK        5504                      // 5504*2048 = 11272192 exactly

__device__ __forceinline__ void make_params(float a, float bt,
                                            float& s, float& qmax)
{
    s = fmaxf(a, 1e-5f);
    const float b = rintf(fminf(fmaxf(fabsf(bt), 1.0f), 6.0f));
    qmax = fmaxf(exp2f(b - 1.0f) - 1.0f, 1.0f);
}

__device__ __forceinline__ float4 quant4(float4 v, float s, float qmax)
{
    const float qmin = -qmax;
    // True IEEE divide: rint decisions must match the reference exactly.
    v.x = fminf(fmaxf(rintf(v.x / s), qmin), qmax) * s;
    v.y = fminf(fmaxf(rintf(v.y / s), qmin), qmax) * s;
    v.z = fminf(fmaxf(rintf(v.z / s), qmin), qmax) * s;
    v.w = fminf(fmaxf(rintf(v.w / s), qmin), qmax) * s;
    return v;
}

__global__ __launch_bounds__(NTHR, 6)
void fake_quant_kernel(const float4* __restrict__ w,
                       const float*  __restrict__ alh,
                       const float*  __restrict__ bit,
                       float4* __restrict__ out)
{
    const unsigned blk_start = blockIdx.x * CHUNK;
    const unsigned base      = blk_start + threadIdx.x;

    // Two candidate rows for this block (uniform -> one udiv per thread,
    // alh/bit loads are broadcast L1 hits).
    const unsigned r0       = blk_start / VEC_PER_ROW;
    const unsigned boundary = (r0 + 1u) * VEC_PER_ROW;
    const unsigned r1       = min(r0 + 1u, LAST_ROW);

    float s0, q0, s1, q1;
    make_params(alh[r0], bit[r0], s0, q0);
    make_params(alh[r1], bit[r1], s1, q1);

    // Front-batch all 8 loads: 8 independent LDG.128 in flight per thread.
    float4 v[BATCH];
    #pragma unroll
    for (int i = 0; i < BATCH; i++)
        v[i] = __ldcs(&w[base + i * NTHR]);

    #pragma unroll
    for (int i = 0; i < BATCH; i++) {
        const unsigned idx = base + i * NTHR;
        const bool hi = idx >= boundary;         // FSEL per item, no udiv
        const float s    = hi ? s1 : s0;
        const float qmax = hi ? q1 : q0;
        __stcs(&out[idx], quant4(v[i], s, qmax));
    }
}

extern "C" void kernel_launch(void* const* d_in, const int* in_sizes, int n_in,
                              void* d_out, int out_size)
{
    const float4* w   = (const float4*)d_in[0];  // weight [4096, 11008]
    const float*  alh = (const float*)d_in[1];   // [4096, 1]
    const float*  bit = (const float*)d_in[2];   // [4096, 1]
    float4* out = (float4*)d_out;

    fake_quant_kernel<<<NBLK, NTHR>>>(w, alh, bit, out);
}